// round 3
// baseline (speedup 1.0000x reference)
#include <cuda_runtime.h>
#include <cuda_bf16.h>
#include <cstdint>

// ---------------- problem constants ----------------
#define BATCH 8
#define CIN 512
#define HH 50
#define WW 50
#define NPX (HH*WW)          // 2500
#define NA 9
#define NANCH (NPX*NA)       // 22500
#define PRE_NMS 1000
#define POST_NMS 300
#define NMS_THR 0.7f
#define IMGF 800.0f
#define MIN_SIZE 16.0f

// ---------------- device scratch (static; no allocations allowed) ----------------
__device__ float g_feat[(size_t)BATCH*CIN*NPX];     // shared conv output (relu'd)
__device__ float g_cls[(size_t)BATCH*NPX*18];
__device__ float g_reg[(size_t)BATCH*NPX*36];
__device__ float g_boxes[(size_t)BATCH*NANCH*4];
__device__ unsigned int g_key[(size_t)BATCH*NANCH]; // monotone score key (0 == invalid)

// ============================================================
// Kernel 1: 3x3 conv 512->512, SAME, +bias, ReLU, fp32
// Two-level accumulation: fp32 within 8-channel chunks (72 terms),
// chunk sums folded into separate fp32 totals (low rounding noise).
// block: 256 threads, tile 64 out-ch x (2 rows x 64 cols)
// thread: 4 k x 8 px
// ============================================================
__global__ __launch_bounds__(256) void conv3x3_kernel(
    const float* __restrict__ x, const float* __restrict__ w, const float* __restrict__ bias)
{
    __shared__ float sIn[8][4][66];   // [cin_chunk][rows(2+halo)][cols(64+halo)]
    __shared__ float sW[8][64][9];    // [cin_chunk][kout][3x3]

    const int r0 = blockIdx.x * 2;    // output row pair
    const int k0 = blockIdx.y * 64;
    const int b  = blockIdx.z;
    const int tid = threadIdx.x;
    const int kg = tid >> 4;          // 0..15, 4 k each
    const int pxg = tid & 15;         // 0..15, 8 px each (2 rows x 4 cols strided 16)

    float tot[4][8];
#pragma unroll
    for (int jj = 0; jj < 4; ++jj)
#pragma unroll
        for (int i = 0; i < 8; ++i) tot[jj][i] = 0.f;

    const float* xb = x + (size_t)b * CIN * NPX;

    for (int ch = 0; ch < CIN / 8; ++ch) {
        const int c0 = ch * 8;
        __syncthreads();
        // load input tile (with zero halo)
        for (int idx = tid; idx < 8 * 4 * 66; idx += 256) {
            int c = idx / 264; int rem = idx % 264;
            int r = rem / 66;  int xx = rem % 66;
            int gy = r0 - 1 + r;
            int gx = xx - 1;
            float v = 0.f;
            if ((unsigned)gy < (unsigned)HH && (unsigned)gx < (unsigned)WW)
                v = xb[(size_t)(c0 + c) * NPX + gy * WW + gx];
            sIn[c][r][xx] = v;
        }
        // load weights
        for (int idx = tid; idx < 8 * 64 * 9; idx += 256) {
            int c = idx / 576; int rem = idx % 576;
            int k = rem / 9;   int q = rem % 9;
            sW[c][k][q] = w[(size_t)(k0 + k) * (CIN * 9) + (size_t)(c0 + c) * 9 + q];
        }
        __syncthreads();

        // chunk accumulators (reset per 8-channel chunk)
        float acc[4][8];
#pragma unroll
        for (int jj = 0; jj < 4; ++jj)
#pragma unroll
            for (int i = 0; i < 8; ++i) acc[jj][i] = 0.f;

        for (int c = 0; c < 8; ++c) {
#pragma unroll
            for (int dy = 0; dy < 3; ++dy) {
#pragma unroll
                for (int dx = 0; dx < 3; ++dx) {
                    float wv[4], iv[8];
#pragma unroll
                    for (int jj = 0; jj < 4; ++jj) wv[jj] = sW[c][kg * 4 + jj][dy * 3 + dx];
#pragma unroll
                    for (int i = 0; i < 8; ++i) {
                        int row = i >> 2;
                        int col = pxg + (i & 3) * 16;
                        iv[i] = sIn[c][row + dy][col + dx];
                    }
#pragma unroll
                    for (int jj = 0; jj < 4; ++jj)
#pragma unroll
                        for (int i = 0; i < 8; ++i)
                            acc[jj][i] = fmaf(wv[jj], iv[i], acc[jj][i]);
                }
            }
        }
        // fold chunk into totals
#pragma unroll
        for (int jj = 0; jj < 4; ++jj)
#pragma unroll
            for (int i = 0; i < 8; ++i) tot[jj][i] += acc[jj][i];
    }

    // epilogue: bias + relu + store
#pragma unroll
    for (int i = 0; i < 8; ++i) {
        int row = r0 + (i >> 2);
        int col = pxg + (i & 3) * 16;
        if (col < WW) {
#pragma unroll
            for (int jj = 0; jj < 4; ++jj) {
                int k = k0 + kg * 4 + jj;
                float v = tot[jj][i] + bias[k];
                v = fmaxf(v, 0.f);
                g_feat[((size_t)b * CIN + k) * NPX + row * WW + col] = v;
            }
        }
    }
}

// ============================================================
// Kernel 2: 1x1 heads (cls 18 + reg 36), fp32, two-level accumulation
// block handles 32 pixels of one image; X staged in 64KB smem
// ============================================================
__global__ __launch_bounds__(256) void heads_kernel(
    const float* __restrict__ wc, const float* __restrict__ bc,
    const float* __restrict__ wr, const float* __restrict__ brg)
{
    extern __shared__ float X[]; // [512][32]
    const int b = blockIdx.y;
    const int p0 = blockIdx.x * 32;
    const int tid = threadIdx.x;

    for (int idx = tid; idx < CIN * 32; idx += 256) {
        int c = idx >> 5; int j = idx & 31;
        int p = p0 + j;
        X[idx] = (p < NPX) ? g_feat[((size_t)b * CIN + c) * NPX + p] : 0.f;
    }
    __syncthreads();

    for (int t = tid; t < 54 * 8; t += 256) {
        int o = t >> 3;
        int j0 = (t & 7) * 4;
        float bb = (o < 18) ? bc[o] : brg[o - 18];
        const float* W = (o < 18) ? (wc + (size_t)o * CIN) : (wr + (size_t)(o - 18) * CIN);
        float t0 = 0.f, t1 = 0.f, t2 = 0.f, t3 = 0.f;
        for (int cc = 0; cc < CIN; cc += 8) {
            float a0 = 0.f, a1 = 0.f, a2 = 0.f, a3 = 0.f;
#pragma unroll
            for (int u = 0; u < 8; ++u) {
                int c = cc + u;
                float wv = __ldg(&W[c]);
                const float4 xv = *(const float4*)&X[c * 32 + j0];
                a0 = fmaf(wv, xv.x, a0);
                a1 = fmaf(wv, xv.y, a1);
                a2 = fmaf(wv, xv.z, a2);
                a3 = fmaf(wv, xv.w, a3);
            }
            t0 += a0; t1 += a1; t2 += a2; t3 += a3;
        }
        float accs[4] = {t0 + bb, t1 + bb, t2 + bb, t3 + bb};
#pragma unroll
        for (int jj = 0; jj < 4; ++jj) {
            int p = p0 + j0 + jj;
            if (p < NPX) {
                if (o < 18) g_cls[((size_t)b * NPX + p) * 18 + o] = accs[jj];
                else        g_reg[((size_t)b * NPX + p) * 36 + (o - 18)] = accs[jj];
            }
        }
    }
}

// ============================================================
// Kernel 3: decode anchors -> boxes, softmax score (jax-style), filter, key
// ============================================================
__global__ __launch_bounds__(256) void decode_kernel()
{
    int g = blockIdx.x * blockDim.x + threadIdx.x;
    if (g >= BATCH * NANCH) return;
    int b = g / NANCH;
    int n = g % NANCH;
    int p = n / NA;
    int a = n % NA;
    int yy = p / WW;
    int xx = p % WW;

    int ri = a / 3, si = a % 3;
    float ratio = (ri == 0) ? 0.5f : (ri == 1 ? 1.0f : 2.0f);
    float scale = (si == 0) ? 8.0f : (si == 1 ? 16.0f : 32.0f);
    float ah = 16.0f * scale * sqrtf(ratio);
    float aw = 16.0f * scale * sqrtf(1.0f / ratio);
    float sy = yy * 16.0f, sx = xx * 16.0f;
    float ay1 = sy + 8.0f - ah * 0.5f;
    float ax1 = sx + 8.0f - aw * 0.5f;
    float ay2 = sy + 8.0f + ah * 0.5f;
    float ax2 = sx + 8.0f + aw * 0.5f;

    float h = ay2 - ay1;
    float w = ax2 - ax1;
    float cy = ay1 + 0.5f * h;
    float cx = ax1 + 0.5f * w;

    const float* rg = &g_reg[((size_t)b * NPX + p) * 36 + a * 4];
    float ncy = rg[0] * h + cy;
    float ncx = rg[1] * w + cx;
    float nh = h * expf(rg[2]);
    float nw = w * expf(rg[3]);

    float y1 = fminf(fmaxf(ncy - 0.5f * nh, 0.f), IMGF);
    float x1 = fminf(fmaxf(ncx - 0.5f * nw, 0.f), IMGF);
    float y2 = fminf(fmaxf(ncy + 0.5f * nh, 0.f), IMGF);
    float x2 = fminf(fmaxf(ncx + 0.5f * nw, 0.f), IMGF);

    float hs = y2 - y1, ws = x2 - x1;
    bool valid = (hs >= MIN_SIZE) && (ws >= MIN_SIZE);

    // softmax over 2 logits, replicated as jax.nn.softmax (max-subtract form)
    const float* cl = &g_cls[((size_t)b * NPX + p) * 18 + a * 2];
    float c0 = cl[0], c1 = cl[1];
    float m = fmaxf(c0, c1);
    float e0 = expf(c0 - m);
    float e1 = expf(c1 - m);
    float score = e1 / (e0 + e1);

    float* bx = &g_boxes[((size_t)b * NANCH + n) * 4];
    bx[0] = y1; bx[1] = x1; bx[2] = y2; bx[3] = x2;
    g_key[(size_t)b * NANCH + n] = valid ? (__float_as_uint(score) | 0x80000000u) : 0u;
}

// ============================================================
// Kernel 4: per-image top-1000 select + sort + greedy NMS + top-300 output
// one block (1024 threads) per image; big dynamic smem
// ============================================================
#define PROP_SMEM (90000 + 16384 + 16000 + 4000 + 4000 + 4096 + 4096 + 4096)

__global__ __launch_bounds__(1024) void propose_kernel(float* __restrict__ out)
{
    extern __shared__ unsigned char smem[];
    unsigned int* skey = (unsigned int*)smem;                       // 22500
    unsigned long long* cand = (unsigned long long*)(smem + 90000); // 2048
    float* sb     = (float*)(smem + 90000 + 16384);                 // [1000][4]
    float* sarea  = sb + 4000;                                      // [1000]
    float* sscore = sarea + 1000;                                   // [1000]
    int*   ssup   = (int*)(sscore + 1000);                          // [1024]
    int*   sA     = ssup + 1024;                                    // [1024]
    int*   sB     = sA + 1024;                                      // [1024]
    __shared__ int s_cnt;
    __shared__ unsigned int s_T;
    __shared__ int s_nc;
    __shared__ int s_NK;

    const int b = blockIdx.x;
    const int tid = threadIdx.x;
    const unsigned int* gk = g_key + (size_t)b * NANCH;

    for (int n = tid; n < NANCH; n += 1024) skey[n] = gk[n];
    if (tid == 0) s_T = 0u;
    __syncthreads();

    // exact 1000th-largest key via bitwise binary search
    for (int bit = 31; bit >= 0; --bit) {
        unsigned int T2 = s_T | (1u << bit);
        if (tid == 0) s_cnt = 0;
        __syncthreads();
        int c = 0;
        for (int n = tid; n < NANCH; n += 1024) c += (skey[n] >= T2) ? 1 : 0;
#pragma unroll
        for (int o = 16; o; o >>= 1) c += __shfl_down_sync(0xFFFFFFFFu, c, o);
        if ((tid & 31) == 0) atomicAdd(&s_cnt, c);
        __syncthreads();
        if (tid == 0 && s_cnt >= PRE_NMS) s_T = T2;
        __syncthreads();
    }
    unsigned int T = s_T;
    if (tid == 0) s_nc = 0;
    __syncthreads();

    // gather candidates (key >= T), packed (key << 32) | ~idx for stable tie-break
    for (int n = tid; n < NANCH; n += 1024) {
        unsigned int k = skey[n];
        if (k >= T) {
            int pos = atomicAdd(&s_nc, 1);
            if (pos < 2048)
                cand[pos] = ((unsigned long long)k << 32) | (unsigned int)(~n);
        }
    }
    __syncthreads();
    int nc = min(s_nc, 2048);
    for (int i = tid; i < 2048; i += 1024)
        if (i >= nc) cand[i] = 0ull;
    __syncthreads();

    // bitonic sort 2048, descending
    for (int k = 2; k <= 2048; k <<= 1) {
        for (int j = k >> 1; j > 0; j >>= 1) {
            __syncthreads();
#pragma unroll
            for (int base = 0; base < 2048; base += 1024) {
                int i = base + tid;
                int ixj = i ^ j;
                if (ixj > i) {
                    unsigned long long a = cand[i], c2 = cand[ixj];
                    bool up = ((i & k) == 0);
                    bool swap = up ? (a < c2) : (a > c2);
                    if (swap) { cand[i] = c2; cand[ixj] = a; }
                }
            }
        }
    }
    __syncthreads();

    // load top-1000 boxes
    if (tid < PRE_NMS) {
        unsigned long long ck = cand[tid];
        unsigned int idx = ~(unsigned int)(ck & 0xFFFFFFFFull);
        if (idx >= (unsigned)NANCH) idx = 0;
        const float* bx = g_boxes + ((size_t)b * NANCH + idx) * 4;
        float y1 = bx[0], x1 = bx[1], y2 = bx[2], x2 = bx[3];
        sb[tid * 4 + 0] = y1; sb[tid * 4 + 1] = x1;
        sb[tid * 4 + 2] = y2; sb[tid * 4 + 3] = x2;
        sarea[tid] = (y2 - y1) * (x2 - x1);
        unsigned int kb = (unsigned int)(ck >> 32);
        sscore[tid] = __uint_as_float(kb ^ 0x80000000u);
    }
    ssup[tid] = 0;
    __syncthreads();

    // greedy NMS (exact reference semantics)
    for (int i = 0; i < PRE_NMS - 1; ++i) {
        if (ssup[i] == 0) {
            int j = tid;
            if (j > i && j < PRE_NMS && ssup[j] == 0) {
                float ty = fmaxf(sb[i * 4 + 0], sb[j * 4 + 0]);
                float tx = fmaxf(sb[i * 4 + 1], sb[j * 4 + 1]);
                float by = fminf(sb[i * 4 + 2], sb[j * 4 + 2]);
                float bxx = fminf(sb[i * 4 + 3], sb[j * 4 + 3]);
                float ih = fmaxf(by - ty, 0.f);
                float iw = fmaxf(bxx - tx, 0.f);
                float inter = ih * iw;
                float iou = inter / (sarea[i] + sarea[j] - inter + 1e-9f);
                if (iou > NMS_THR) ssup[j] = 1;
            }
        }
        __syncthreads();
    }

    // keep flags + inclusive prefix sum (Hillis-Steele)
    int keepv = (tid < PRE_NMS) ? (ssup[tid] ? 0 : 1) : 0;
    sA[tid] = keepv;
    __syncthreads();
    int* src = sA; int* dst = sB;
    for (int d = 1; d < 1024; d <<= 1) {
        int v = src[tid];
        if (tid >= d) v += src[tid - d];
        dst[tid] = v;
        __syncthreads();
        int* t = src; src = dst; dst = t;
    }
    if (tid == 0) s_NK = src[PRE_NMS - 1];
    __syncthreads();
    int NK = s_NK;

    // write: kept boxes in order, then (if NK<300) suppressed in positional order w/ -1e30
    float* ob = out + (size_t)b * POST_NMS * 5;
    if (tid < PRE_NMS) {
        int incl = src[tid];
        int excl = incl - keepv;
        int slot; float sc;
        if (keepv) { slot = excl; sc = sscore[tid]; }
        else       { slot = NK + (tid - excl); sc = -1e30f; }
        if (slot < POST_NMS) {
            ob[slot * 5 + 0] = sb[tid * 4 + 0];
            ob[slot * 5 + 1] = sb[tid * 4 + 1];
            ob[slot * 5 + 2] = sb[tid * 4 + 2];
            ob[slot * 5 + 3] = sb[tid * 4 + 3];
            ob[slot * 5 + 4] = sc;
        }
    }
}

// ============================================================
extern "C" void kernel_launch(void* const* d_in, const int* in_sizes, int n_in,
                              void* d_out, int out_size)
{
    const float* x       = (const float*)d_in[0];
    const float* w_share = (const float*)d_in[1];
    const float* b_share = (const float*)d_in[2];
    const float* w_cls   = (const float*)d_in[3];
    const float* b_cls   = (const float*)d_in[4];
    const float* w_reg   = (const float*)d_in[5];
    const float* b_reg   = (const float*)d_in[6];
    float* out = (float*)d_out;

    cudaFuncSetAttribute(heads_kernel, cudaFuncAttributeMaxDynamicSharedMemorySize, CIN * 32 * 4);
    cudaFuncSetAttribute(propose_kernel, cudaFuncAttributeMaxDynamicSharedMemorySize, PROP_SMEM);

    conv3x3_kernel<<<dim3(HH / 2, CIN / 64, BATCH), 256>>>(x, w_share, b_share);
    heads_kernel<<<dim3((NPX + 31) / 32, BATCH), 256, CIN * 32 * 4>>>(w_cls, b_cls, w_reg, b_reg);
    decode_kernel<<<(BATCH * NANCH + 255) / 256, 256>>>();
    propose_kernel<<<BATCH, 1024, PROP_SMEM>>>(out);
}